// round 3
// baseline (speedup 1.0000x reference)
#include <cuda_runtime.h>
#include <cuda_bf16.h>

#define B     64
#define S     512
#define TF    1024
#define TD    128
#define V     1000
#define KW    31
#define PAD   15
#define TT    32   // t-tile in scores kernel

// ---------------- scratch (device globals; no allocation allowed) ----------------
__device__ float g_keysT[(size_t)B * S * TF];   // keys transposed: [b][s][t]
__device__ float g_h[B * S];
__device__ float g_ctx[B * S];
__device__ float g_q[B * S];                    // q + bq + conv_b folded
__device__ float g_gi[B * 3 * S];
__device__ float g_gh[B * 3 * S];
__device__ float g_scores[B * TF];
__device__ float g_w[B * TF];
__device__ float g_cwT[KW * S];                 // conv filters transposed: [k][s]

// ---------------- helpers ----------------
__device__ __forceinline__ float fast_tanh(float x) {
    float e = __expf(2.0f * x);
    return 1.0f - 2.0f / (e + 1.0f);
}
__device__ __forceinline__ float fast_sigmoid(float x) {
    return 1.0f / (1.0f + __expf(-x));
}

// ---------------- init: zero recurrent state ----------------
__global__ void init_kernel() {
    int idx = blockIdx.x * 256 + threadIdx.x;
    if (idx < B * S) { g_h[idx] = 0.0f; g_ctx[idx] = 0.0f; }
    if (idx < B * TF) g_w[idx] = 0.0f;
}

// ---------------- transpose conv filters: [s][k] -> [k][s] ----------------
__global__ void cw_transpose_kernel(const float* __restrict__ conv_w) {
    int idx = blockIdx.x * 256 + threadIdx.x;
    if (idx < S * KW) {
        int s = idx / KW, k = idx % KW;
        g_cwT[k * S + s] = conv_w[idx];
    }
}

// ---------------- keys precompute: keysT[b][n][t] = sum_k F[b,t,k]*Wk[n,k] + bk[n] ----------------
// GEMM: M = B*TF (=65536) rows of features, N = S, K = S. 64x64 tile, 256 thr, 4x4/thread.
__global__ __launch_bounds__(256) void keys_gemm_kernel(
    const float* __restrict__ features, const float* __restrict__ Wk,
    const float* __restrict__ bk)
{
    __shared__ float As[16][68];
    __shared__ float Bs[16][68];
    int tid = threadIdx.x;
    int m0 = blockIdx.x * 64, n0 = blockIdx.y * 64;
    int lr = tid & 63, lk = tid >> 6;     // load row, k-segment (0..3)
    int tx = tid & 15, ty = tid >> 4;     // compute coords
    float c[4][4] = {};

    for (int k0 = 0; k0 < S; k0 += 16) {
        float4 a = *(const float4*)(features + (size_t)(m0 + lr) * S + k0 + lk * 4);
        float4 bv = *(const float4*)(Wk + (size_t)(n0 + lr) * S + k0 + lk * 4);
        __syncthreads();
        As[lk * 4 + 0][lr] = a.x;  As[lk * 4 + 1][lr] = a.y;
        As[lk * 4 + 2][lr] = a.z;  As[lk * 4 + 3][lr] = a.w;
        Bs[lk * 4 + 0][lr] = bv.x; Bs[lk * 4 + 1][lr] = bv.y;
        Bs[lk * 4 + 2][lr] = bv.z; Bs[lk * 4 + 3][lr] = bv.w;
        __syncthreads();
#pragma unroll
        for (int k = 0; k < 16; k++) {
            float4 av = *(const float4*)&As[k][ty * 4];
            float4 bw = *(const float4*)&Bs[k][tx * 4];
            c[0][0] = fmaf(av.x, bw.x, c[0][0]); c[0][1] = fmaf(av.x, bw.y, c[0][1]);
            c[0][2] = fmaf(av.x, bw.z, c[0][2]); c[0][3] = fmaf(av.x, bw.w, c[0][3]);
            c[1][0] = fmaf(av.y, bw.x, c[1][0]); c[1][1] = fmaf(av.y, bw.y, c[1][1]);
            c[1][2] = fmaf(av.y, bw.z, c[1][2]); c[1][3] = fmaf(av.y, bw.w, c[1][3]);
            c[2][0] = fmaf(av.z, bw.x, c[2][0]); c[2][1] = fmaf(av.z, bw.y, c[2][1]);
            c[2][2] = fmaf(av.z, bw.z, c[2][2]); c[2][3] = fmaf(av.z, bw.w, c[2][3]);
            c[3][0] = fmaf(av.w, bw.x, c[3][0]); c[3][1] = fmaf(av.w, bw.y, c[3][1]);
            c[3][2] = fmaf(av.w, bw.z, c[3][2]); c[3][3] = fmaf(av.w, bw.w, c[3][3]);
        }
    }
    int bb = m0 >> 10;                  // whole tile lies within one b (64 | 1024)
    int tbase = (m0 & 1023) + ty * 4;
#pragma unroll
    for (int j = 0; j < 4; j++) {
        int n = n0 + tx * 4 + j;
        float bias = bk[n];
        float* dst = g_keysT + ((size_t)bb * S + n) * TF + tbase;
#pragma unroll
        for (int i = 0; i < 4; i++) dst[i] = c[i][j] + bias;
    }
}

// ---------------- skinny step GEMM (M=64), NT layout: C = A @ B^T + bias ----------------
// mode 0: gi  = x @ W_ih^T + b_ih     (x = [emb_t | ctx], K=1024, N=1536) -> g_gi
// mode 1: gh  = h @ W_hh^T + b_hh     (K=512,  N=1536)                    -> g_gh
// mode 2: q'  = h @ Wq^T + bq + conv_b (K=512, N=512)                     -> g_q
// mode 3: out = [h|ctx] @ Wo^T + bo   (K=1024, N=1000)                    -> outs[:, t, :]
//
// mode_base = 0: prologue, modes {0,1} via blockIdx.y, gates at t_gates
// mode_base = 2: q only
// mode_base = 3: combined: y==0 -> logits at t_logits; y==1 -> mode 0 at t_gates;
//                y==2 -> mode 1. (logits_t and gates_{t+1} both depend only on h_t, ctx_t)
__global__ __launch_bounds__(256) void step_gemm_kernel(
    int mode_base,
    const int* __restrict__ input_ids, const float* __restrict__ emb,
    const float* __restrict__ W_ih, const float* __restrict__ W_hh,
    const float* __restrict__ b_ih, const float* __restrict__ b_hh,
    const float* __restrict__ Wq, const float* __restrict__ bq,
    const float* __restrict__ conv_b,
    const float* __restrict__ Wo, const float* __restrict__ bo,
    float* __restrict__ outs, int t_logits, int t_gates)
{
    int mode;
    if (mode_base == 0)      mode = blockIdx.y;                       // 0 or 1
    else if (mode_base == 2) mode = 2;
    else                     mode = (blockIdx.y == 0) ? 3 : (int)blockIdx.y - 1;

    int K, N;
    const float* Bm;
    const float* bias;
    if (mode == 0)      { K = 1024; N = 3 * S; Bm = W_ih; bias = b_ih; }
    else if (mode == 1) { K = 512;  N = 3 * S; Bm = W_hh; bias = b_hh; }
    else if (mode == 2) { K = 512;  N = S;     Bm = Wq;   bias = bq;   }
    else                { K = 1024; N = V;     Bm = Wo;   bias = bo;   }

    int n0 = blockIdx.x * 32;
    if (n0 >= N) return;     // combined launch uses max grid.x across modes

    __shared__ float As[32][68];
    __shared__ float Bs[32][34];
    __shared__ int s_idx[64];

    int tid = threadIdx.x;
    if (mode == 0 && tid < 64) s_idx[tid] = input_ids[tid * TD + t_gates];
    __syncthreads();

    int tx = tid & 15, ty = tid >> 4;      // n = n0 + tx*2 + {0,1}, m = ty*4 + {0..3}
    int am = tid & 63, akseg = tid >> 6;   // A loads: row am, k chunk of 8
    int bn = tid & 31, bkseg = tid >> 5;   // B loads: row bn, k chunk of 4
    float c[4][2] = {};

    for (int k0 = 0; k0 < K; k0 += 32) {
        int kbase = k0 + akseg * 8;
        const float* ap;
        if (mode == 0) {
            if (kbase < 512) ap = emb + (size_t)s_idx[am] * S + kbase;
            else             ap = g_ctx + am * S + (kbase - 512);
        } else if (mode == 3) {
            if (kbase < 512) ap = g_h + am * S + kbase;
            else             ap = g_ctx + am * S + (kbase - 512);
        } else {
            ap = g_h + am * S + kbase;
        }
        float4 a0 = *(const float4*)ap;
        float4 a1 = *(const float4*)(ap + 4);

        int gn = n0 + bn;
        float4 bv = make_float4(0.f, 0.f, 0.f, 0.f);
        if (gn < N) bv = *(const float4*)(Bm + (size_t)gn * K + k0 + bkseg * 4);

        __syncthreads();
        As[akseg * 8 + 0][am] = a0.x; As[akseg * 8 + 1][am] = a0.y;
        As[akseg * 8 + 2][am] = a0.z; As[akseg * 8 + 3][am] = a0.w;
        As[akseg * 8 + 4][am] = a1.x; As[akseg * 8 + 5][am] = a1.y;
        As[akseg * 8 + 6][am] = a1.z; As[akseg * 8 + 7][am] = a1.w;
        Bs[bkseg * 4 + 0][bn] = bv.x; Bs[bkseg * 4 + 1][bn] = bv.y;
        Bs[bkseg * 4 + 2][bn] = bv.z; Bs[bkseg * 4 + 3][bn] = bv.w;
        __syncthreads();
#pragma unroll
        for (int k = 0; k < 32; k++) {
            float4 a = *(const float4*)&As[k][ty * 4];
            float2 b = *(const float2*)&Bs[k][tx * 2];
            c[0][0] = fmaf(a.x, b.x, c[0][0]); c[0][1] = fmaf(a.x, b.y, c[0][1]);
            c[1][0] = fmaf(a.y, b.x, c[1][0]); c[1][1] = fmaf(a.y, b.y, c[1][1]);
            c[2][0] = fmaf(a.z, b.x, c[2][0]); c[2][1] = fmaf(a.z, b.y, c[2][1]);
            c[3][0] = fmaf(a.w, b.x, c[3][0]); c[3][1] = fmaf(a.w, b.y, c[3][1]);
        }
    }

#pragma unroll
    for (int i = 0; i < 4; i++) {
#pragma unroll
        for (int j = 0; j < 2; j++) {
            int gn = n0 + tx * 2 + j;
            int m = ty * 4 + i;
            float bv = (gn < N) ? bias[gn] : 0.0f;
            float val = c[i][j] + bv;
            if (mode == 0)      g_gi[m * (3 * S) + gn] = val;
            else if (mode == 1) g_gh[m * (3 * S) + gn] = val;
            else if (mode == 2) g_q[m * S + gn] = val + conv_b[gn];
            else if (gn < N)
                outs[((size_t)m * TD + t_logits) * (size_t)V + gn] = val;
        }
    }
}

// ---------------- GRU gate combine ----------------
__global__ __launch_bounds__(256) void h_update_kernel() {
    int idx = blockIdx.x * 256 + threadIdx.x;   // B*S = 32768
    int b = idx >> 9, j = idx & 511;
    int base = b * (3 * S);
    float gir = g_gi[base + j], giz = g_gi[base + 512 + j], gin = g_gi[base + 1024 + j];
    float ghr = g_gh[base + j], ghz = g_gh[base + 512 + j], ghn = g_gh[base + 1024 + j];
    float r = fast_sigmoid(gir + ghr);
    float z = fast_sigmoid(giz + ghz);
    float n = fast_tanh(gin + r * ghn);
    float h = g_h[idx];
    g_h[idx] = (1.0f - z) * n + z * h;
}

// ---------------- attention scores: fused location-conv + tanh + v-dot ----------------
// scores[b,t] = sum_s v[s]*tanh(q'[b,s] + keysT[b,s,t] + sum_k cw[s,k]*w_prev[b,t+k-PAD])
// block = (t-tile of 32, b), 512 threads (one per s). Thread keeps 31 taps + 32 accs in regs.
__global__ __launch_bounds__(512) void scores_kernel(const float* __restrict__ v_vec) {
    const int b = blockIdx.y;
    const int t0 = blockIdx.x * TT;
    const int s = threadIdx.x;

    __shared__ float s_win[TT + KW - 1];   // 62
    __shared__ float s_red[16][TT + 1];

    if (s < TT + KW - 1) {
        int t = t0 + s - PAD;
        s_win[s] = (t >= 0 && t < TF) ? g_w[b * TF + t] : 0.0f;
    }
    __syncthreads();

    float cw[KW];
#pragma unroll
    for (int k = 0; k < KW; k++) cw[k] = g_cwT[k * S + s];
    float qv = g_q[b * S + s];
    float vs = v_vec[s];

    float acc[TT];
    const float* kp = g_keysT + ((size_t)b * S + s) * TF + t0;
#pragma unroll
    for (int j = 0; j < TT; j += 4) {
        float4 kv = *(const float4*)(kp + j);
        acc[j + 0] = qv + kv.x; acc[j + 1] = qv + kv.y;
        acc[j + 2] = qv + kv.z; acc[j + 3] = qv + kv.w;
    }
    // diagonal ordering: one broadcast LDS per window element (62 total)
#pragma unroll
    for (int i = 0; i < TT + KW - 1; i++) {
        float wv = s_win[i];
#pragma unroll
        for (int j = 0; j < TT; j++) {
            int k = i - j;
            if (k >= 0 && k < KW) acc[j] = fmaf(cw[k], wv, acc[j]);
        }
    }
    // tanh, weight by v[s], reduce over s (warp butterfly + smem combine)
#pragma unroll
    for (int j = 0; j < TT; j++) {
        float e = __expf(2.0f * acc[j]);
        float cval = vs * (1.0f - 2.0f / (e + 1.0f));
#pragma unroll
        for (int off = 16; off > 0; off >>= 1)
            cval += __shfl_xor_sync(0xffffffffu, cval, off);
        acc[j] = cval;
    }
    int warp = s >> 5, lane = s & 31;
    if (lane == 0) {
#pragma unroll
        for (int j = 0; j < TT; j++) s_red[warp][j] = acc[j];
    }
    __syncthreads();
    if (s < TT) {
        float sum = 0.0f;
#pragma unroll
        for (int w = 0; w < 16; w++) sum += s_red[w][s];
        g_scores[b * TF + t0 + s] = sum;
    }
}

// ---------------- softmax over Tf; writes g_w and ws output ----------------
__global__ __launch_bounds__(256) void softmax_kernel(float* __restrict__ ws, int t_step) {
    int b = blockIdx.x, tid = threadIdx.x;
    __shared__ float s_r[8];
    float vals[4];
    float m = -1e30f;
#pragma unroll
    for (int i = 0; i < 4; i++) {
        vals[i] = g_scores[b * TF + tid + i * 256];
        m = fmaxf(m, vals[i]);
    }
#pragma unroll
    for (int off = 16; off > 0; off >>= 1)
        m = fmaxf(m, __shfl_xor_sync(0xffffffffu, m, off));
    if ((tid & 31) == 0) s_r[tid >> 5] = m;
    __syncthreads();
    m = s_r[0];
#pragma unroll
    for (int w = 1; w < 8; w++) m = fmaxf(m, s_r[w]);
    __syncthreads();

    float sum = 0.0f;
#pragma unroll
    for (int i = 0; i < 4; i++) { vals[i] = __expf(vals[i] - m); sum += vals[i]; }
#pragma unroll
    for (int off = 16; off > 0; off >>= 1)
        sum += __shfl_xor_sync(0xffffffffu, sum, off);
    if ((tid & 31) == 0) s_r[tid >> 5] = sum;
    __syncthreads();
    float total = 0.0f;
#pragma unroll
    for (int w = 0; w < 8; w++) total += s_r[w];
    float inv = 1.0f / total;
#pragma unroll
    for (int i = 0; i < 4; i++) {
        int t = tid + i * 256;
        float wv = vals[i] * inv;
        g_w[b * TF + t] = wv;
        ws[((size_t)b * TD + t_step) * (size_t)TF + t] = wv;
    }
}

// ---------------- context: ctx[b,d] = sum_t w[b,t] * features[b,t,d] ----------------
__global__ __launch_bounds__(128) void ctx_kernel(const float* __restrict__ features) {
    int b = blockIdx.y;
    int d = blockIdx.x * 128 + threadIdx.x;
    __shared__ float s_w[TF];
    for (int i = threadIdx.x; i < TF; i += 128) s_w[i] = g_w[b * TF + i];
    __syncthreads();
    const float* f = features + (size_t)b * TF * S + d;
    float a0 = 0.f, a1 = 0.f, a2 = 0.f, a3 = 0.f;
#pragma unroll 2
    for (int t = 0; t < TF; t += 4) {
        a0 = fmaf(s_w[t + 0], f[(size_t)(t + 0) * S], a0);
        a1 = fmaf(s_w[t + 1], f[(size_t)(t + 1) * S], a1);
        a2 = fmaf(s_w[t + 2], f[(size_t)(t + 2) * S], a2);
        a3 = fmaf(s_w[t + 3], f[(size_t)(t + 3) * S], a3);
    }
    g_ctx[b * S + d] = (a0 + a1) + (a2 + a3);
}

// ---------------- launch ----------------
extern "C" void kernel_launch(void* const* d_in, const int* in_sizes, int n_in,
                              void* d_out, int out_size) {
    const int*   input    = (const int*)d_in[0];
    const float* features = (const float*)d_in[1];
    const float* emb      = (const float*)d_in[2];
    const float* W_ih     = (const float*)d_in[3];
    const float* W_hh     = (const float*)d_in[4];
    const float* b_ih     = (const float*)d_in[5];
    const float* b_hh     = (const float*)d_in[6];
    const float* Wq       = (const float*)d_in[7];
    const float* bq       = (const float*)d_in[8];
    const float* Wk       = (const float*)d_in[9];
    const float* bk       = (const float*)d_in[10];
    const float* conv_w   = (const float*)d_in[11];
    const float* conv_b   = (const float*)d_in[12];
    const float* v_vec    = (const float*)d_in[13];
    const float* Wo       = (const float*)d_in[14];
    const float* bo       = (const float*)d_in[15];

    float* outs = (float*)d_out;                        // [B, TD, V]
    float* ws   = outs + (size_t)B * TD * V;            // [B, TD, TF]

    init_kernel<<<(B * TF + 255) / 256, 256>>>();
    cw_transpose_kernel<<<(S * KW + 255) / 256, 256>>>(conv_w);
    keys_gemm_kernel<<<dim3((B * TF) / 64, S / 64), 256>>>(features, Wk, bk);

    // prologue: gi/gh for t=0 (h0 = ctx0 = 0)
    step_gemm_kernel<<<dim3((3 * S) / 32, 2), 256>>>(
        0, input, emb, W_ih, W_hh, b_ih, b_hh, Wq, bq, conv_b, Wo, bo, outs, 0, 0);

    for (int t = 0; t < TD; ++t) {
        h_update_kernel<<<(B * S) / 256, 256>>>();
        // q = h @ Wq^T + bq + conv_b (mode 2)
        step_gemm_kernel<<<dim3(S / 32, 1), 256>>>(
            2, input, emb, W_ih, W_hh, b_ih, b_hh, Wq, bq, conv_b, Wo, bo, outs, t, t);
        scores_kernel<<<dim3(TF / TT, B), 512>>>(v_vec);
        softmax_kernel<<<B, 256>>>(ws, t);
        ctx_kernel<<<dim3(S / 128, B), 128>>>(features);
        // combined: logits_t (+ gi/gh for t+1 when t < TD-1)
        int gy = (t < TD - 1) ? 3 : 1;
        step_gemm_kernel<<<dim3((3 * S) / 32, gy), 256>>>(
            3, input, emb, W_ih, W_hh, b_ih, b_hh, Wq, bq, conv_b, Wo, bo, outs, t, t + 1);
    }
}